// round 13
// baseline (speedup 1.0000x reference)
#include <cuda_runtime.h>
#include <cuda_bf16.h>
#include <cstdint>
#include <cstddef>

#define BB 64
#define TT 1024
#define HH 64
#define G3 192
#define NB 4                              // batches per GRU block
#define ATT_SCALE 0.17677669529663687f   // 1/sqrt(32)

typedef unsigned long long ull;

// ---------------- packed f32x2 helpers (GRU dots) ----------------
__device__ __forceinline__ ull ffma2(ull a, ull b, ull c) {
    ull d; asm("fma.rn.f32x2 %0, %1, %2, %3;" : "=l"(d) : "l"(a), "l"(b), "l"(c)); return d;
}
__device__ __forceinline__ ull pack2(float lo, float hi) {
    ull d; asm("mov.b64 %0, {%1, %2};" : "=l"(d) : "f"(lo), "f"(hi)); return d;
}
__device__ __forceinline__ float2 unpack2(ull a) {
    float lo, hi; asm("mov.b64 {%0, %1}, %2;" : "=f"(lo), "=f"(hi) : "l"(a));
    return make_float2(lo, hi);
}
__device__ __forceinline__ float hsum2(ull a) { float2 v = unpack2(a); return v.x + v.y; }

// ---------------- scratch (static device globals, no allocation) ----------------
__device__ float g_bufA[(size_t)BB * TT * G3];   // xw0 -> qkv1 -> qkv2
__device__ float g_bufB[(size_t)BB * TT * HH];   // gru out -> a1
__device__ float g_bufC[(size_t)BB * TT * HH];   // attn1 out

// ---------------- math helpers ----------------
__device__ __forceinline__ float sigmoidf_(float x) {
    x = fminf(fmaxf(x, -30.f), 30.f);
    return __fdividef(1.f, 1.f + __expf(-x));
}
__device__ __forceinline__ float tanhf_(float x) {
    x = fminf(fmaxf(x, -15.f), 15.f);
    return __fdividef(2.f, 1.f + __expf(-2.f * x)) - 1.f;
}

// =====================================================================
// kernel 1: embed + rbf + x @ w_ih0^T + b_ih0   -> xw0 (B*T, 192)
// =====================================================================
__global__ __launch_bounds__(192) void k_embed(
        const int* __restrict__ atom_idx, const float* __restrict__ bond,
        const float* __restrict__ emb, const float* __restrict__ w_ih0,
        const float* __restrict__ b_ih0, float* __restrict__ xw0) {
    __shared__ float wsT[30][192];
    __shared__ float xs[16][30];
    int tid = threadIdx.x;
    int pos0 = blockIdx.x * 16;
    for (int idx = tid; idx < 192 * 30; idx += 192) {
        int g = idx / 30, d = idx % 30;
        wsT[d][g] = w_ih0[idx];
    }
    for (int idx = tid; idx < 16 * 30; idx += 192) {
        int p = idx / 30, d = idx % 30;
        int pos = pos0 + p;
        int ii = atom_idx[pos * 2 + 0];
        int jj = atom_idx[pos * 2 + 1];
        float v;
        if (d < 10) {
            v = (ii != 0) ? emb[ii * 10 + d] : 0.f;
        } else if (d < 20) {
            v = (jj != 0) ? emb[jj * 10 + (d - 10)] : 0.f;
        } else {
            float dd = bond[pos];
            float c = (float)(d - 20 + 1);
            float t = c - dd;
            v = (ii != 0) ? expf(-t * t) : 0.f;
        }
        xs[p][d] = v;
    }
    __syncthreads();
    float bb = b_ih0[tid];
    for (int p = 0; p < 16; p++) {
        float acc = bb;
        #pragma unroll
        for (int d = 0; d < 30; d++) acc += xs[p][d] * wsT[d][tid];
        xw0[(size_t)(pos0 + p) * G3 + tid] = acc;
    }
}

// =====================================================================
// kernel 2: fused 2-layer GRU, BATCHED: NB=4 molecules per block.
// grid B/NB = 16, block 576 (same group structure as the proven R5 kernel):
//   tid   0..191 : W_hh0 row g  -> a0[nb][g]
//   tid 192..383 : W_ih1 row g  -> x1[nb][g]
//   tid 384..575 : W_hh1 row g  -> g1a[nb][g]
// Weights in registers (64 regs), h reads are warp-broadcast LDS.64.
// Gate phase: threads 0..255 layer0 (nb,j), threads 256..511 layer1 (nb,j).
// =====================================================================
__global__ __launch_bounds__(576, 1) void k_gru(
        const float* __restrict__ xw0,
        const float* __restrict__ w_hh0, const float* __restrict__ b_hh0,
        const float* __restrict__ w_ih1, const float* __restrict__ b_ih1,
        const float* __restrict__ w_hh1, const float* __restrict__ b_hh1,
        float* __restrict__ outp) {
    int b0 = blockIdx.x * NB;
    int tid = threadIdx.x;
    __shared__ __align__(16) float h0[NB][HH];
    __shared__ __align__(16) float h1[NB][HH];
    __shared__ float a0s[NB][G3];
    __shared__ float xn0[NB][HH];
    __shared__ float x1s[NB][G3];
    __shared__ float g1s[NB][G3];

    int grp = tid / 192;
    int g = tid - grp * 192;
    const float* wsrc = (grp == 0) ? w_hh0 : ((grp == 1) ? w_ih1 : w_hh1);
    const float* bsrc = (grp == 0) ? b_hh0 : ((grp == 1) ? b_ih1 : b_hh1);
    ull w2[32];
    const ull* wp = (const ull*)(wsrc + (size_t)g * 64);
    #pragma unroll
    for (int i = 0; i < 32; i++) w2[i] = __ldg(wp + i);
    float bias = __ldg(bsrc + g);

    for (int idx = tid; idx < NB * HH; idx += 576) {
        ((float*)h0)[idx] = 0.f;
        ((float*)h1)[idx] = 0.f;
    }
    __syncthreads();

    // x prefetch (grp0 only): one value per batch
    float xv[NB];
    #pragma unroll
    for (int nb = 0; nb < NB; nb++)
        xv[nb] = (grp == 0) ? xw0[((size_t)(b0 + nb) * TT) * G3 + g] : 0.f;

    for (int t = 0; t <= TT; t++) {
        // ---- dot phase: each thread, its gate row vs NB h-vectors ----
        if (grp == 0) {
            if (t < TT) {
                float xcur[NB];
                #pragma unroll
                for (int nb = 0; nb < NB; nb++) {
                    xcur[nb] = xv[nb];
                    if (t + 1 < TT)
                        xv[nb] = xw0[((size_t)(b0 + nb) * TT + t + 1) * G3 + g];
                }
                ull acc[NB][2];
                #pragma unroll
                for (int nb = 0; nb < NB; nb++) { acc[nb][0] = pack2(bias, 0.f); acc[nb][1] = 0ull; }
                #pragma unroll
                for (int i = 0; i < 32; i += 2) {
                    #pragma unroll
                    for (int nb = 0; nb < NB; nb++) {
                        const ull* hp = (const ull*)h0[nb];
                        acc[nb][0] = ffma2(w2[i], hp[i], acc[nb][0]);
                        acc[nb][1] = ffma2(w2[i + 1], hp[i + 1], acc[nb][1]);
                    }
                }
                #pragma unroll
                for (int nb = 0; nb < NB; nb++) {
                    float v = hsum2(acc[nb][0]) + hsum2(acc[nb][1]);
                    if (g < 128) {
                        a0s[nb][g] = sigmoidf_(xcur[nb] + v);
                    } else {
                        a0s[nb][g] = v;
                        xn0[nb][g - 128] = xcur[nb];
                    }
                }
            }
        } else {
            if (t >= 1) {
                bool ih = (grp == 1);
                ull acc[NB][2];
                #pragma unroll
                for (int nb = 0; nb < NB; nb++) { acc[nb][0] = pack2(bias, 0.f); acc[nb][1] = 0ull; }
                #pragma unroll
                for (int i = 0; i < 32; i += 2) {
                    #pragma unroll
                    for (int nb = 0; nb < NB; nb++) {
                        const ull* hp = (const ull*)(ih ? h0[nb] : h1[nb]);
                        acc[nb][0] = ffma2(w2[i], hp[i], acc[nb][0]);
                        acc[nb][1] = ffma2(w2[i + 1], hp[i + 1], acc[nb][1]);
                    }
                }
                #pragma unroll
                for (int nb = 0; nb < NB; nb++) {
                    float v = hsum2(acc[nb][0]) + hsum2(acc[nb][1]);
                    if (ih) x1s[nb][g] = v; else g1s[nb][g] = v;
                }
            }
        }
        __syncthreads();
        // ---- gate phase ----
        if (tid < NB * HH) {
            if (t < TT) {
                int nb = tid >> 6, j = tid & 63;
                float r = a0s[nb][j], z = a0s[nb][64 + j];
                float hn = a0s[nb][128 + j], xn = xn0[nb][j];
                float n = tanhf_(xn + r * hn);
                h0[nb][j] = (1.f - z) * n + z * h0[nb][j];
            }
        } else if (tid < 2 * NB * HH) {
            if (t >= 1) {
                int u = tid - NB * HH;
                int nb = u >> 6, j = u & 63;
                float r = sigmoidf_(x1s[nb][j] + g1s[nb][j]);
                float z = sigmoidf_(x1s[nb][64 + j] + g1s[nb][64 + j]);
                float n = tanhf_(x1s[nb][128 + j] + r * g1s[nb][128 + j]);
                float hv = (1.f - z) * n + z * h1[nb][j];
                h1[nb][j] = hv;
                outp[((size_t)(b0 + nb) * TT + (t - 1)) * HH + j] = hv;
            }
        }
        __syncthreads();
    }
}

// =====================================================================
// kernel 3: C[N,M] = A[N,64] @ W[M,64]^T + bias  (known-good scalar)
// =====================================================================
__global__ __launch_bounds__(256) void k_gemm(
        const float* __restrict__ A, const float* __restrict__ W,
        const float* __restrict__ bias, float* __restrict__ C, int M) {
    __shared__ __align__(16) float As[64][65];
    __shared__ __align__(16) float Ws[64][65];
    int r0 = blockIdx.x * 64, c0 = blockIdx.y * 64;
    int tid = threadIdx.x;
    int tx = tid & 15, ty = tid >> 4;
    for (int idx = tid; idx < 4096; idx += 256) {
        int r = idx >> 6, k = idx & 63;
        As[r][k] = A[(size_t)(r0 + r) * 64 + k];
        Ws[r][k] = W[(size_t)(c0 + r) * 64 + k];
    }
    __syncthreads();
    float acc[4][4];
    #pragma unroll
    for (int j = 0; j < 4; j++) {
        float bv = bias[c0 + tx * 4 + j];
        #pragma unroll
        for (int i = 0; i < 4; i++) acc[i][j] = bv;
    }
    #pragma unroll 8
    for (int k = 0; k < 64; k++) {
        float a0 = As[ty * 4 + 0][k], a1 = As[ty * 4 + 1][k];
        float a2 = As[ty * 4 + 2][k], a3 = As[ty * 4 + 3][k];
        float w0 = Ws[tx * 4 + 0][k], w1 = Ws[tx * 4 + 1][k];
        float w2 = Ws[tx * 4 + 2][k], w3 = Ws[tx * 4 + 3][k];
        acc[0][0] += a0 * w0; acc[0][1] += a0 * w1; acc[0][2] += a0 * w2; acc[0][3] += a0 * w3;
        acc[1][0] += a1 * w0; acc[1][1] += a1 * w1; acc[1][2] += a1 * w2; acc[1][3] += a1 * w3;
        acc[2][0] += a2 * w0; acc[2][1] += a2 * w1; acc[2][2] += a2 * w2; acc[2][3] += a2 * w3;
        acc[3][0] += a3 * w0; acc[3][1] += a3 * w1; acc[3][2] += a3 * w2; acc[3][3] += a3 * w3;
    }
    #pragma unroll
    for (int i = 0; i < 4; i++)
        #pragma unroll
        for (int j = 0; j < 4; j++)
            C[(size_t)(r0 + ty * 4 + i) * M + c0 + tx * 4 + j] = acc[i][j];
}

// =====================================================================
// kernel 4: flash attention (layer 1) — R11 winner, unchanged.
// =====================================================================
__global__ __launch_bounds__(256) void k_flash(const float* __restrict__ qkv,
                                               float* __restrict__ outp) {
    __shared__ __align__(16) float Qs[64][36];
    __shared__ __align__(16) float KsT[32][68];
    __shared__ __align__(16) float Vs[64][36];
    __shared__ __align__(16) float Ps[64][68];
    int bid = blockIdx.x;
    int qt = bid & 15, h = (bid >> 4) & 1, b = bid >> 5;
    int tid = threadIdx.x, tx = tid & 15, ty = tid >> 4;
    const float* base = qkv + (size_t)b * TT * G3;

    for (int idx = tid; idx < 512; idx += 256) {
        int qi = idx >> 3, f4 = idx & 7;
        float4 v = *(const float4*)&base[(size_t)(qt * 64 + qi) * G3 + h * 32 + f4 * 4];
        *(float4*)&Qs[qi][f4 * 4] = v;
    }
    float m[4], l[4];
    float2 o[4];
    #pragma unroll
    for (int i = 0; i < 4; i++) { m[i] = -1e30f; l[i] = 0.f; o[i] = make_float2(0.f, 0.f); }
    __syncthreads();

    for (int kt = 0; kt < 16; kt++) {
        for (int idx = tid; idx < 512; idx += 256) {
            int ki = idx >> 3, f4 = idx & 7;
            int d0 = f4 * 4;
            const float* row = base + (size_t)(kt * 64 + ki) * G3 + h * 32;
            float4 kv = *(const float4*)&row[64 + d0];
            KsT[d0 + 0][ki] = kv.x;
            KsT[d0 + 1][ki] = kv.y;
            KsT[d0 + 2][ki] = kv.z;
            KsT[d0 + 3][ki] = kv.w;
            float4 vv = *(const float4*)&row[128 + d0];
            *(float4*)&Vs[ki][d0] = vv;
        }
        __syncthreads();

        float s[4][4];
        #pragma unroll
        for (int i = 0; i < 4; i++)
            #pragma unroll
            for (int j = 0; j < 4; j++) s[i][j] = 0.f;
        #pragma unroll
        for (int d0 = 0; d0 < 32; d0 += 4) {
            float4 q0 = *(const float4*)&Qs[ty * 4 + 0][d0];
            float4 q1 = *(const float4*)&Qs[ty * 4 + 1][d0];
            float4 q2 = *(const float4*)&Qs[ty * 4 + 2][d0];
            float4 q3 = *(const float4*)&Qs[ty * 4 + 3][d0];
            float4 k0 = *(const float4*)&KsT[d0 + 0][tx * 4];
            float4 k1 = *(const float4*)&KsT[d0 + 1][tx * 4];
            float4 k2 = *(const float4*)&KsT[d0 + 2][tx * 4];
            float4 k3 = *(const float4*)&KsT[d0 + 3][tx * 4];
            s[0][0] += q0.x * k0.x; s[0][1] += q0.x * k0.y; s[0][2] += q0.x * k0.z; s[0][3] += q0.x * k0.w;
            s[1][0] += q1.x * k0.x; s[1][1] += q1.x * k0.y; s[1][2] += q1.x * k0.z; s[1][3] += q1.x * k0.w;
            s[2][0] += q2.x * k0.x; s[2][1] += q2.x * k0.y; s[2][2] += q2.x * k0.z; s[2][3] += q2.x * k0.w;
            s[3][0] += q3.x * k0.x; s[3][1] += q3.x * k0.y; s[3][2] += q3.x * k0.z; s[3][3] += q3.x * k0.w;
            s[0][0] += q0.y * k1.x; s[0][1] += q0.y * k1.y; s[0][2] += q0.y * k1.z; s[0][3] += q0.y * k1.w;
            s[1][0] += q1.y * k1.x; s[1][1] += q1.y * k1.y; s[1][2] += q1.y * k1.z; s[1][3] += q1.y * k1.w;
            s[2][0] += q2.y * k1.x; s[2][1] += q2.y * k1.y; s[2][2] += q2.y * k1.z; s[2][3] += q2.y * k1.w;
            s[3][0] += q3.y * k1.x; s[3][1] += q3.y * k1.y; s[3][2] += q3.y * k1.z; s[3][3] += q3.y * k1.w;
            s[0][0] += q0.z * k2.x; s[0][1] += q0.z * k2.y; s[0][2] += q0.z * k2.z; s[0][3] += q0.z * k2.w;
            s[1][0] += q1.z * k2.x; s[1][1] += q1.z * k2.y; s[1][2] += q1.z * k2.z; s[1][3] += q1.z * k2.w;
            s[2][0] += q2.z * k2.x; s[2][1] += q2.z * k2.y; s[2][2] += q2.z * k2.z; s[2][3] += q2.z * k2.w;
            s[3][0] += q3.z * k2.x; s[3][1] += q3.z * k2.y; s[3][2] += q3.z * k2.z; s[3][3] += q3.z * k2.w;
            s[0][0] += q0.w * k3.x; s[0][1] += q0.w * k3.y; s[0][2] += q0.w * k3.z; s[0][3] += q0.w * k3.w;
            s[1][0] += q1.w * k3.x; s[1][1] += q1.w * k3.y; s[1][2] += q1.w * k3.z; s[1][3] += q1.w * k3.w;
            s[2][0] += q2.w * k3.x; s[2][1] += q2.w * k3.y; s[2][2] += q2.w * k3.z; s[2][3] += q2.w * k3.w;
            s[3][0] += q3.w * k3.x; s[3][1] += q3.w * k3.y; s[3][2] += q3.w * k3.z; s[3][3] += q3.w * k3.w;
        }
        #pragma unroll
        for (int i = 0; i < 4; i++) {
            #pragma unroll
            for (int j = 0; j < 4; j++) s[i][j] *= ATT_SCALE;
            float rm = fmaxf(fmaxf(s[i][0], s[i][1]), fmaxf(s[i][2], s[i][3]));
            rm = fmaxf(rm, __shfl_xor_sync(0xFFFFFFFFu, rm, 1));
            rm = fmaxf(rm, __shfl_xor_sync(0xFFFFFFFFu, rm, 2));
            rm = fmaxf(rm, __shfl_xor_sync(0xFFFFFFFFu, rm, 4));
            rm = fmaxf(rm, __shfl_xor_sync(0xFFFFFFFFu, rm, 8));
            float mn = fmaxf(m[i], rm);
            float alpha = __expf(m[i] - mn);
            float p0 = __expf(s[i][0] - mn), p1 = __expf(s[i][1] - mn);
            float p2 = __expf(s[i][2] - mn), p3 = __expf(s[i][3] - mn);
            float rs = (p0 + p1) + (p2 + p3);
            rs += __shfl_xor_sync(0xFFFFFFFFu, rs, 1);
            rs += __shfl_xor_sync(0xFFFFFFFFu, rs, 2);
            rs += __shfl_xor_sync(0xFFFFFFFFu, rs, 4);
            rs += __shfl_xor_sync(0xFFFFFFFFu, rs, 8);
            l[i] = l[i] * alpha + rs;
            o[i].x *= alpha; o[i].y *= alpha;
            m[i] = mn;
            Ps[ty * 4 + i][tx * 4 + 0] = p0;
            Ps[ty * 4 + i][tx * 4 + 1] = p1;
            Ps[ty * 4 + i][tx * 4 + 2] = p2;
            Ps[ty * 4 + i][tx * 4 + 3] = p3;
        }
        __syncthreads();
        #pragma unroll
        for (int kk = 0; kk < 64; kk += 4) {
            float4 p0 = *(const float4*)&Ps[ty * 4 + 0][kk];
            float4 p1 = *(const float4*)&Ps[ty * 4 + 1][kk];
            float4 p2 = *(const float4*)&Ps[ty * 4 + 2][kk];
            float4 p3 = *(const float4*)&Ps[ty * 4 + 3][kk];
            float2 v0 = *(const float2*)&Vs[kk + 0][tx * 2];
            float2 v1 = *(const float2*)&Vs[kk + 1][tx * 2];
            float2 v2 = *(const float2*)&Vs[kk + 2][tx * 2];
            float2 v3 = *(const float2*)&Vs[kk + 3][tx * 2];
            o[0].x += p0.x * v0.x; o[0].y += p0.x * v0.y;
            o[1].x += p1.x * v0.x; o[1].y += p1.x * v0.y;
            o[2].x += p2.x * v0.x; o[2].y += p2.x * v0.y;
            o[3].x += p3.x * v0.x; o[3].y += p3.x * v0.y;
            o[0].x += p0.y * v1.x; o[0].y += p0.y * v1.y;
            o[1].x += p1.y * v1.x; o[1].y += p1.y * v1.y;
            o[2].x += p2.y * v1.x; o[2].y += p2.y * v1.y;
            o[3].x += p3.y * v1.x; o[3].y += p3.y * v1.y;
            o[0].x += p0.z * v2.x; o[0].y += p0.z * v2.y;
            o[1].x += p1.z * v2.x; o[1].y += p1.z * v2.y;
            o[2].x += p2.z * v2.x; o[2].y += p2.z * v2.y;
            o[3].x += p3.z * v2.x; o[3].y += p3.z * v2.y;
            o[0].x += p0.w * v3.x; o[0].y += p0.w * v3.y;
            o[1].x += p1.w * v3.x; o[1].y += p1.w * v3.y;
            o[2].x += p2.w * v3.x; o[2].y += p2.w * v3.y;
            o[3].x += p3.w * v3.x; o[3].y += p3.w * v3.y;
        }
        __syncthreads();
    }
    #pragma unroll
    for (int i = 0; i < 4; i++) {
        float inv = __fdividef(1.f, l[i]);
        int qg = qt * 64 + ty * 4 + i;
        float* dst = outp + (size_t)(b * TT + qg) * HH + h * 32 + tx * 2;
        dst[0] = o[i].x * inv;
        dst[1] = o[i].y * inv;
    }
}

// =====================================================================
// kernel 5: last-token attention-2 + out_proj2 + ReLU MLP head
// =====================================================================
__global__ __launch_bounds__(256) void k_final(
        const float* __restrict__ qkv2,
        const float* __restrict__ out_w2, const float* __restrict__ out_b2,
        const float* __restrict__ w_l, const float* __restrict__ b_l,
        const float* __restrict__ w_l1, const float* __restrict__ b_l1,
        float* __restrict__ out) {
    int b = blockIdx.x, tid = threadIdx.x;
    __shared__ float q2s[64];
    __shared__ float sc[2][1024];
    __shared__ float red[256];
    __shared__ float sh2[2];
    __shared__ float os[64], a2s[64], hs[32];
    const float* base = qkv2 + (size_t)b * TT * G3;
    if (tid < 64) q2s[tid] = base[(size_t)(TT - 1) * G3 + tid];
    __syncthreads();
    for (int t = tid; t < 1024; t += 256) {
        const float* row = base + (size_t)t * G3 + 64;
        float a0 = 0.f, a1 = 0.f;
        #pragma unroll 8
        for (int d = 0; d < 32; d++) {
            a0 += q2s[d] * row[d];
            a1 += q2s[32 + d] * row[32 + d];
        }
        sc[0][t] = a0 * ATT_SCALE;
        sc[1][t] = a1 * ATT_SCALE;
    }
    __syncthreads();
    for (int h = 0; h < 2; h++) {
        float mloc = -1e30f;
        for (int t = tid; t < 1024; t += 256) mloc = fmaxf(mloc, sc[h][t]);
        red[tid] = mloc;
        __syncthreads();
        for (int s = 128; s > 0; s >>= 1) {
            if (tid < s) red[tid] = fmaxf(red[tid], red[tid + s]);
            __syncthreads();
        }
        float mh = red[0];
        __syncthreads();
        float sum = 0.f;
        for (int t = tid; t < 1024; t += 256) {
            float e = __expf(sc[h][t] - mh);
            sc[h][t] = e;
            sum += e;
        }
        red[tid] = sum;
        __syncthreads();
        for (int s = 128; s > 0; s >>= 1) {
            if (tid < s) red[tid] += red[tid + s];
            __syncthreads();
        }
        if (tid == 0) sh2[h] = red[0];
        __syncthreads();
    }
    if (tid < 64) {
        int h = tid >> 5;
        const float* vcol = base + 128 + tid;
        float acc = 0.f;
        #pragma unroll 8
        for (int t = 0; t < 1024; t++) acc += sc[h][t] * vcol[(size_t)t * G3];
        os[tid] = acc / sh2[h];
    }
    __syncthreads();
    if (tid < 64) {
        float acc = out_b2[tid];
        #pragma unroll 8
        for (int d = 0; d < 64; d++) acc += os[d] * out_w2[tid * 64 + d];
        a2s[tid] = acc;
    }
    __syncthreads();
    if (tid < 32) {
        float acc = b_l[tid];
        #pragma unroll 8
        for (int d = 0; d < 64; d++) acc += a2s[d] * w_l[tid * 64 + d];
        hs[tid] = fmaxf(acc, 0.f);
    }
    __syncthreads();
    if (tid == 0) {
        float acc = b_l1[0];
        #pragma unroll
        for (int c = 0; c < 32; c++) acc += hs[c] * w_l1[c];
        out[b] = acc;
    }
}

// =====================================================================
extern "C" void kernel_launch(void* const* d_in, const int* in_sizes, int n_in,
                              void* d_out, int out_size) {
    const int*   atom_idx = (const int*)  d_in[0];
    const float* bond     = (const float*)d_in[1];
    const float* emb      = (const float*)d_in[2];
    const float* w_ih0    = (const float*)d_in[3];
    const float* w_hh0    = (const float*)d_in[4];
    const float* b_ih0    = (const float*)d_in[5];
    const float* b_hh0    = (const float*)d_in[6];
    const float* w_ih1    = (const float*)d_in[7];
    const float* w_hh1    = (const float*)d_in[8];
    const float* b_ih1    = (const float*)d_in[9];
    const float* b_hh1    = (const float*)d_in[10];
    const float* in_w1    = (const float*)d_in[11];
    const float* in_b1    = (const float*)d_in[12];
    const float* out_w1   = (const float*)d_in[13];
    const float* out_b1   = (const float*)d_in[14];
    const float* in_w2    = (const float*)d_in[15];
    const float* in_b2    = (const float*)d_in[16];
    const float* out_w2   = (const float*)d_in[17];
    const float* out_b2   = (const float*)d_in[18];
    const float* w_l      = (const float*)d_in[19];
    const float* b_l      = (const float*)d_in[20];
    const float* w_l1     = (const float*)d_in[21];
    const float* b_l1     = (const float*)d_in[22];
    float* outp = (float*)d_out;

    float *bufA, *bufB, *bufC;
    cudaGetSymbolAddress((void**)&bufA, g_bufA);
    cudaGetSymbolAddress((void**)&bufB, g_bufB);
    cudaGetSymbolAddress((void**)&bufC, g_bufC);

    k_embed<<<(BB * TT) / 16, 192>>>(atom_idx, bond, emb, w_ih0, b_ih0, bufA);
    k_gru<<<BB / NB, 576>>>(bufA, w_hh0, b_hh0, w_ih1, b_ih1, w_hh1, b_hh1, bufB);
    {
        dim3 g((BB * TT) / 64, 3);
        k_gemm<<<g, 256>>>(bufB, in_w1, in_b1, bufA, G3);
    }
    k_flash<<<BB * 2 * (TT / 64), 256>>>(bufA, bufC);
    {
        dim3 g((BB * TT) / 64, 1);
        k_gemm<<<g, 256>>>(bufC, out_w1, out_b1, bufB, HH);
    }
    {
        dim3 g((BB * TT) / 64, 3);
        k_gemm<<<g, 256>>>(bufB, in_w2, in_b2, bufA, G3);
    }
    k_final<<<BB, 256>>>(bufA, out_w2, out_b2, w_l, b_l, w_l1, b_l1, outp);
}

// round 14
// speedup vs baseline: 4.6390x; 4.6390x over previous
#include <cuda_runtime.h>
#include <cuda_bf16.h>
#include <cstdint>
#include <cstddef>

#define BB 64
#define TT 1024
#define HH 64
#define G3 192
#define ATT_SCALE 0.17677669529663687f   // 1/sqrt(32)

typedef unsigned long long ull;

// ---------------- packed f32x2 helpers (GRU dots) ----------------
__device__ __forceinline__ ull ffma2(ull a, ull b, ull c) {
    ull d; asm("fma.rn.f32x2 %0, %1, %2, %3;" : "=l"(d) : "l"(a), "l"(b), "l"(c)); return d;
}
__device__ __forceinline__ ull pack2(float lo, float hi) {
    ull d; asm("mov.b64 %0, {%1, %2};" : "=l"(d) : "f"(lo), "f"(hi)); return d;
}
__device__ __forceinline__ float2 unpack2(ull a) {
    float lo, hi; asm("mov.b64 {%0, %1}, %2;" : "=f"(lo), "=f"(hi) : "l"(a));
    return make_float2(lo, hi);
}
__device__ __forceinline__ float hsum2(ull a) { float2 v = unpack2(a); return v.x + v.y; }

// ---------------- scratch (static device globals, no allocation) ----------------
__device__ float g_bufA[(size_t)BB * TT * G3];   // xw0 -> qkv1 -> qkv2
__device__ float g_bufB[(size_t)BB * TT * HH];   // gru out
__device__ float g_bufC[(size_t)BB * TT * HH];   // attn1 out
__device__ float g_wc[G3 * HH];                  // fused W = in_w2 @ out_w1
__device__ float g_bc[G3];                       // fused bias = in_w2 @ out_b1 + in_b2

// ---------------- math helpers ----------------
__device__ __forceinline__ float sigmoidf_(float x) {
    x = fminf(fmaxf(x, -30.f), 30.f);
    return __fdividef(1.f, 1.f + __expf(-x));
}
__device__ __forceinline__ float tanhf_(float x) {
    x = fminf(fmaxf(x, -15.f), 15.f);
    return __fdividef(2.f, 1.f + __expf(-2.f * x)) - 1.f;
}

// =====================================================================
// kernel 1: embed + rbf + x @ w_ih0^T + b_ih0   -> xw0 (B*T, 192)
// =====================================================================
__global__ __launch_bounds__(192) void k_embed(
        const int* __restrict__ atom_idx, const float* __restrict__ bond,
        const float* __restrict__ emb, const float* __restrict__ w_ih0,
        const float* __restrict__ b_ih0, float* __restrict__ xw0) {
    __shared__ float wsT[30][192];
    __shared__ float xs[16][30];
    int tid = threadIdx.x;
    int pos0 = blockIdx.x * 16;
    for (int idx = tid; idx < 192 * 30; idx += 192) {
        int g = idx / 30, d = idx % 30;
        wsT[d][g] = w_ih0[idx];
    }
    for (int idx = tid; idx < 16 * 30; idx += 192) {
        int p = idx / 30, d = idx % 30;
        int pos = pos0 + p;
        int ii = atom_idx[pos * 2 + 0];
        int jj = atom_idx[pos * 2 + 1];
        float v;
        if (d < 10) {
            v = (ii != 0) ? emb[ii * 10 + d] : 0.f;
        } else if (d < 20) {
            v = (jj != 0) ? emb[jj * 10 + (d - 10)] : 0.f;
        } else {
            float dd = bond[pos];
            float c = (float)(d - 20 + 1);
            float t = c - dd;
            v = (ii != 0) ? expf(-t * t) : 0.f;
        }
        xs[p][d] = v;
    }
    __syncthreads();
    float bb = b_ih0[tid];
    for (int p = 0; p < 16; p++) {
        float acc = bb;
        #pragma unroll
        for (int d = 0; d < 30; d++) acc += xs[p][d] * wsT[d][tid];
        xw0[(size_t)(pos0 + p) * G3 + tid] = acc;
    }
}

// =====================================================================
// kernel 1b: fuse out-proj1 + qkv2 weights:
//   Wc[m][k] = sum_j in_w2[m][j] * out_w1[j][k]   (192 x 64)
//   bc[m]    = sum_j in_w2[m][j] * out_b1[j] + in_b2[m]
// grid 48, block 256: each thread one Wc element.
// =====================================================================
__global__ __launch_bounds__(256) void k_fuse(
        const float* __restrict__ in_w2, const float* __restrict__ in_b2,
        const float* __restrict__ out_w1, const float* __restrict__ out_b1,
        float* __restrict__ wc, float* __restrict__ bc) {
    __shared__ float w1s[64][65];   // [j][k]
    __shared__ float b1s[64];
    int tid = threadIdx.x;
    for (int idx = tid; idx < 4096; idx += 256) {
        int j = idx >> 6, k = idx & 63;
        w1s[j][k] = out_w1[idx];
    }
    if (tid < 64) b1s[tid] = out_b1[tid];
    __syncthreads();
    int gid = blockIdx.x * 256 + tid;        // 0..12287
    int m = gid >> 6, k = gid & 63;
    const float* w2row = in_w2 + (size_t)m * 64;
    float acc = 0.f;
    #pragma unroll 8
    for (int j = 0; j < 64; j++) acc += w2row[j] * w1s[j][k];
    wc[gid] = acc;
    if (k == 0) {
        float bacc = in_b2[m];
        #pragma unroll 8
        for (int j = 0; j < 64; j++) bacc += w2row[j] * b1s[j];
        bc[m] = bacc;
    }
}

// =====================================================================
// kernel 2: fused 2-layer GRU (R11 winner, frozen). 576 threads, 64 blocks.
// =====================================================================
__device__ __forceinline__ float dot64p(const ull* __restrict__ w2,
                                        const float* __restrict__ hsh, float bias) {
    const ull* hp = (const ull*)hsh;
    ull a0 = pack2(bias, 0.f), a1 = 0ull, a2 = 0ull, a3 = 0ull;
    #pragma unroll
    for (int i = 0; i < 32; i += 4) {
        a0 = ffma2(w2[i + 0], hp[i + 0], a0);
        a1 = ffma2(w2[i + 1], hp[i + 1], a1);
        a2 = ffma2(w2[i + 2], hp[i + 2], a2);
        a3 = ffma2(w2[i + 3], hp[i + 3], a3);
    }
    return (hsum2(a0) + hsum2(a1)) + (hsum2(a2) + hsum2(a3));
}

__global__ __launch_bounds__(576, 1) void k_gru(
        const float* __restrict__ xw0,
        const float* __restrict__ w_hh0, const float* __restrict__ b_hh0,
        const float* __restrict__ w_ih1, const float* __restrict__ b_ih1,
        const float* __restrict__ w_hh1, const float* __restrict__ b_hh1,
        float* __restrict__ outp) {
    int b = blockIdx.x;
    int tid = threadIdx.x;
    __shared__ __align__(16) float h0[HH];
    __shared__ __align__(16) float h1[HH];
    __shared__ float a0[G3];
    __shared__ float xn0[HH];
    __shared__ float x1[G3];
    __shared__ float g1a[G3];

    int grp = tid / 192;
    int g = tid - grp * 192;
    const float* wsrc = (grp == 0) ? w_hh0 : ((grp == 1) ? w_ih1 : w_hh1);
    const float* bsrc = (grp == 0) ? b_hh0 : ((grp == 1) ? b_ih1 : b_hh1);
    ull w2[32];
    const ull* wp = (const ull*)(wsrc + (size_t)g * 64);
    #pragma unroll
    for (int i = 0; i < 32; i++) w2[i] = __ldg(wp + i);
    float bias = __ldg(bsrc + g);

    if (tid < HH) { h0[tid] = 0.f; h1[tid] = 0.f; }
    __syncthreads();

    const float* xrow = xw0 + (size_t)b * TT * G3;
    float xv = (grp == 0) ? xrow[g] : 0.f;

    for (int t = 0; t <= TT; t++) {
        if (grp == 0) {
            if (t < TT) {
                float xcur = xv;
                if (t + 1 < TT) xv = xrow[(size_t)(t + 1) * G3 + g];
                float acc = dot64p(w2, h0, bias);
                if (g < 128) {
                    a0[g] = sigmoidf_(xcur + acc);
                } else {
                    a0[g] = acc;
                    xn0[g - 128] = xcur;
                }
            }
        } else if (grp == 1) {
            if (t >= 1) x1[g] = dot64p(w2, h0, bias);
        } else {
            if (t >= 1) g1a[g] = dot64p(w2, h1, bias);
        }
        __syncthreads();
        if (tid < HH) {
            if (t < TT) {
                int j = tid;
                float r = a0[j], z = a0[64 + j], hn = a0[128 + j], xn = xn0[j];
                float n = tanhf_(xn + r * hn);
                h0[j] = (1.f - z) * n + z * h0[j];
            }
        } else if (tid < 2 * HH) {
            if (t >= 1) {
                int j = tid - HH;
                float r = sigmoidf_(x1[j] + g1a[j]);
                float z = sigmoidf_(x1[64 + j] + g1a[64 + j]);
                float n = tanhf_(x1[128 + j] + r * g1a[128 + j]);
                float hv = (1.f - z) * n + z * h1[j];
                h1[j] = hv;
                outp[((size_t)b * TT + (t - 1)) * HH + j] = hv;
            }
        }
        __syncthreads();
    }
}

// =====================================================================
// kernel 3: C[N,M] = A[N,64] @ W[M,64]^T + bias  (known-good scalar)
// =====================================================================
__global__ __launch_bounds__(256) void k_gemm(
        const float* __restrict__ A, const float* __restrict__ W,
        const float* __restrict__ bias, float* __restrict__ C, int M) {
    __shared__ __align__(16) float As[64][65];
    __shared__ __align__(16) float Ws[64][65];
    int r0 = blockIdx.x * 64, c0 = blockIdx.y * 64;
    int tid = threadIdx.x;
    int tx = tid & 15, ty = tid >> 4;
    for (int idx = tid; idx < 4096; idx += 256) {
        int r = idx >> 6, k = idx & 63;
        As[r][k] = A[(size_t)(r0 + r) * 64 + k];
        Ws[r][k] = W[(size_t)(c0 + r) * 64 + k];
    }
    __syncthreads();
    float acc[4][4];
    #pragma unroll
    for (int j = 0; j < 4; j++) {
        float bv = bias[c0 + tx * 4 + j];
        #pragma unroll
        for (int i = 0; i < 4; i++) acc[i][j] = bv;
    }
    #pragma unroll 8
    for (int k = 0; k < 64; k++) {
        float a0 = As[ty * 4 + 0][k], a1 = As[ty * 4 + 1][k];
        float a2 = As[ty * 4 + 2][k], a3 = As[ty * 4 + 3][k];
        float w0 = Ws[tx * 4 + 0][k], w1 = Ws[tx * 4 + 1][k];
        float w2 = Ws[tx * 4 + 2][k], w3 = Ws[tx * 4 + 3][k];
        acc[0][0] += a0 * w0; acc[0][1] += a0 * w1; acc[0][2] += a0 * w2; acc[0][3] += a0 * w3;
        acc[1][0] += a1 * w0; acc[1][1] += a1 * w1; acc[1][2] += a1 * w2; acc[1][3] += a1 * w3;
        acc[2][0] += a2 * w0; acc[2][1] += a2 * w1; acc[2][2] += a2 * w2; acc[2][3] += a2 * w3;
        acc[3][0] += a3 * w0; acc[3][1] += a3 * w1; acc[3][2] += a3 * w2; acc[3][3] += a3 * w3;
    }
    #pragma unroll
    for (int i = 0; i < 4; i++)
        #pragma unroll
        for (int j = 0; j < 4; j++)
            C[(size_t)(r0 + ty * 4 + i) * M + c0 + tx * 4 + j] = acc[i][j];
}

// =====================================================================
// kernel 4: flash attention (layer 1) — R11 winner, unchanged.
// =====================================================================
__global__ __launch_bounds__(256) void k_flash(const float* __restrict__ qkv,
                                               float* __restrict__ outp) {
    __shared__ __align__(16) float Qs[64][36];
    __shared__ __align__(16) float KsT[32][68];
    __shared__ __align__(16) float Vs[64][36];
    __shared__ __align__(16) float Ps[64][68];
    int bid = blockIdx.x;
    int qt = bid & 15, h = (bid >> 4) & 1, b = bid >> 5;
    int tid = threadIdx.x, tx = tid & 15, ty = tid >> 4;
    const float* base = qkv + (size_t)b * TT * G3;

    for (int idx = tid; idx < 512; idx += 256) {
        int qi = idx >> 3, f4 = idx & 7;
        float4 v = *(const float4*)&base[(size_t)(qt * 64 + qi) * G3 + h * 32 + f4 * 4];
        *(float4*)&Qs[qi][f4 * 4] = v;
    }
    float m[4], l[4];
    float2 o[4];
    #pragma unroll
    for (int i = 0; i < 4; i++) { m[i] = -1e30f; l[i] = 0.f; o[i] = make_float2(0.f, 0.f); }
    __syncthreads();

    for (int kt = 0; kt < 16; kt++) {
        for (int idx = tid; idx < 512; idx += 256) {
            int ki = idx >> 3, f4 = idx & 7;
            int d0 = f4 * 4;
            const float* row = base + (size_t)(kt * 64 + ki) * G3 + h * 32;
            float4 kv = *(const float4*)&row[64 + d0];
            KsT[d0 + 0][ki] = kv.x;
            KsT[d0 + 1][ki] = kv.y;
            KsT[d0 + 2][ki] = kv.z;
            KsT[d0 + 3][ki] = kv.w;
            float4 vv = *(const float4*)&row[128 + d0];
            *(float4*)&Vs[ki][d0] = vv;
        }
        __syncthreads();

        float s[4][4];
        #pragma unroll
        for (int i = 0; i < 4; i++)
            #pragma unroll
            for (int j = 0; j < 4; j++) s[i][j] = 0.f;
        #pragma unroll
        for (int d0 = 0; d0 < 32; d0 += 4) {
            float4 q0 = *(const float4*)&Qs[ty * 4 + 0][d0];
            float4 q1 = *(const float4*)&Qs[ty * 4 + 1][d0];
            float4 q2 = *(const float4*)&Qs[ty * 4 + 2][d0];
            float4 q3 = *(const float4*)&Qs[ty * 4 + 3][d0];
            float4 k0 = *(const float4*)&KsT[d0 + 0][tx * 4];
            float4 k1 = *(const float4*)&KsT[d0 + 1][tx * 4];
            float4 k2 = *(const float4*)&KsT[d0 + 2][tx * 4];
            float4 k3 = *(const float4*)&KsT[d0 + 3][tx * 4];
            s[0][0] += q0.x * k0.x; s[0][1] += q0.x * k0.y; s[0][2] += q0.x * k0.z; s[0][3] += q0.x * k0.w;
            s[1][0] += q1.x * k0.x; s[1][1] += q1.x * k0.y; s[1][2] += q1.x * k0.z; s[1][3] += q1.x * k0.w;
            s[2][0] += q2.x * k0.x; s[2][1] += q2.x * k0.y; s[2][2] += q2.x * k0.z; s[2][3] += q2.x * k0.w;
            s[3][0] += q3.x * k0.x; s[3][1] += q3.x * k0.y; s[3][2] += q3.x * k0.z; s[3][3] += q3.x * k0.w;
            s[0][0] += q0.y * k1.x; s[0][1] += q0.y * k1.y; s[0][2] += q0.y * k1.z; s[0][3] += q0.y * k1.w;
            s[1][0] += q1.y * k1.x; s[1][1] += q1.y * k1.y; s[1][2] += q1.y * k1.z; s[1][3] += q1.y * k1.w;
            s[2][0] += q2.y * k1.x; s[2][1] += q2.y * k1.y; s[2][2] += q2.y * k1.z; s[2][3] += q2.y * k1.w;
            s[3][0] += q3.y * k1.x; s[3][1] += q3.y * k1.y; s[3][2] += q3.y * k1.z; s[3][3] += q3.y * k1.w;
            s[0][0] += q0.z * k2.x; s[0][1] += q0.z * k2.y; s[0][2] += q0.z * k2.z; s[0][3] += q0.z * k2.w;
            s[1][0] += q1.z * k2.x; s[1][1] += q1.z * k2.y; s[1][2] += q1.z * k2.z; s[1][3] += q1.z * k2.w;
            s[2][0] += q2.z * k2.x; s[2][1] += q2.z * k2.y; s[2][2] += q2.z * k2.z; s[2][3] += q2.z * k2.w;
            s[3][0] += q3.z * k2.x; s[3][1] += q3.z * k2.y; s[3][2] += q3.z * k2.z; s[3][3] += q3.z * k2.w;
            s[0][0] += q0.w * k3.x; s[0][1] += q0.w * k3.y; s[0][2] += q0.w * k3.z; s[0][3] += q0.w * k3.w;
            s[1][0] += q1.w * k3.x; s[1][1] += q1.w * k3.y; s[1][2] += q1.w * k3.z; s[1][3] += q1.w * k3.w;
            s[2][0] += q2.w * k3.x; s[2][1] += q2.w * k3.y; s[2][2] += q2.w * k3.z; s[2][3] += q2.w * k3.w;
            s[3][0] += q3.w * k3.x; s[3][1] += q3.w * k3.y; s[3][2] += q3.w * k3.z; s[3][3] += q3.w * k3.w;
        }
        #pragma unroll
        for (int i = 0; i < 4; i++) {
            #pragma unroll
            for (int j = 0; j < 4; j++) s[i][j] *= ATT_SCALE;
            float rm = fmaxf(fmaxf(s[i][0], s[i][1]), fmaxf(s[i][2], s[i][3]));
            rm = fmaxf(rm, __shfl_xor_sync(0xFFFFFFFFu, rm, 1));
            rm = fmaxf(rm, __shfl_xor_sync(0xFFFFFFFFu, rm, 2));
            rm = fmaxf(rm, __shfl_xor_sync(0xFFFFFFFFu, rm, 4));
            rm = fmaxf(rm, __shfl_xor_sync(0xFFFFFFFFu, rm, 8));
            float mn = fmaxf(m[i], rm);
            float alpha = __expf(m[i] - mn);
            float p0 = __expf(s[i][0] - mn), p1 = __expf(s[i][1] - mn);
            float p2 = __expf(s[i][2] - mn), p3 = __expf(s[i][3] - mn);
            float rs = (p0 + p1) + (p2 + p3);
            rs += __shfl_xor_sync(0xFFFFFFFFu, rs, 1);
            rs += __shfl_xor_sync(0xFFFFFFFFu, rs, 2);
            rs += __shfl_xor_sync(0xFFFFFFFFu, rs, 4);
            rs += __shfl_xor_sync(0xFFFFFFFFu, rs, 8);
            l[i] = l[i] * alpha + rs;
            o[i].x *= alpha; o[i].y *= alpha;
            m[i] = mn;
            Ps[ty * 4 + i][tx * 4 + 0] = p0;
            Ps[ty * 4 + i][tx * 4 + 1] = p1;
            Ps[ty * 4 + i][tx * 4 + 2] = p2;
            Ps[ty * 4 + i][tx * 4 + 3] = p3;
        }
        __syncthreads();
        #pragma unroll
        for (int kk = 0; kk < 64; kk += 4) {
            float4 p0 = *(const float4*)&Ps[ty * 4 + 0][kk];
            float4 p1 = *(const float4*)&Ps[ty * 4 + 1][kk];
            float4 p2 = *(const float4*)&Ps[ty * 4 + 2][kk];
            float4 p3 = *(const float4*)&Ps[ty * 4 + 3][kk];
            float2 v0 = *(const float2*)&Vs[kk + 0][tx * 2];
            float2 v1 = *(const float2*)&Vs[kk + 1][tx * 2];
            float2 v2 = *(const float2*)&Vs[kk + 2][tx * 2];
            float2 v3 = *(const float2*)&Vs[kk + 3][tx * 2];
            o[0].x += p0.x * v0.x; o[0].y += p0.x * v0.y;
            o[1].x += p1.x * v0.x; o[1].y += p1.x * v0.y;
            o[2].x += p2.x * v0.x; o[2].y += p2.x * v0.y;
            o[3].x += p3.x * v0.x; o[3].y += p3.x * v0.y;
            o[0].x += p0.y * v1.x; o[0].y += p0.y * v1.y;
            o[1].x += p1.y * v1.x; o[1].y += p1.y * v1.y;
            o[2].x += p2.y * v1.x; o[2].y += p2.y * v1.y;
            o[3].x += p3.y * v1.x; o[3].y += p3.y * v1.y;
            o[0].x += p0.z * v2.x; o[0].y += p0.z * v2.y;
            o[1].x += p1.z * v2.x; o[1].y += p1.z * v2.y;
            o[2].x += p2.z * v2.x; o[2].y += p2.z * v2.y;
            o[3].x += p3.z * v2.x; o[3].y += p3.z * v2.y;
            o[0].x += p0.w * v3.x; o[0].y += p0.w * v3.y;
            o[1].x += p1.w * v3.x; o[1].y += p1.w * v3.y;
            o[2].x += p2.w * v3.x; o[2].y += p2.w * v3.y;
            o[3].x += p3.w * v3.x; o[3].y += p3.w * v3.y;
        }
        __syncthreads();
    }
    #pragma unroll
    for (int i = 0; i < 4; i++) {
        float inv = __fdividef(1.f, l[i]);
        int qg = qt * 64 + ty * 4 + i;
        float* dst = outp + (size_t)(b * TT + qg) * HH + h * 32 + tx * 2;
        dst[0] = o[i].x * inv;
        dst[1] = o[i].y * inv;
    }
}

// =====================================================================
// kernel 5: last-token attention-2 + out_proj2 + ReLU MLP head
// =====================================================================
__global__ __launch_bounds__(256) void k_final(
        const float* __restrict__ qkv2,
        const float* __restrict__ out_w2, const float* __restrict__ out_b2,
        const float* __restrict__ w_l, const float* __restrict__ b_l,
        const float* __restrict__ w_l1, const float* __restrict__ b_l1,
        float* __restrict__ out) {
    int b = blockIdx.x, tid = threadIdx.x;
    __shared__ float q2s[64];
    __shared__ float sc[2][1024];
    __shared__ float red[256];
    __shared__ float sh2[2];
    __shared__ float os[64], a2s[64], hs[32];
    const float* base = qkv2 + (size_t)b * TT * G3;
    if (tid < 64) q2s[tid] = base[(size_t)(TT - 1) * G3 + tid];
    __syncthreads();
    for (int t = tid; t < 1024; t += 256) {
        const float* row = base + (size_t)t * G3 + 64;
        float a0 = 0.f, a1 = 0.f;
        #pragma unroll 8
        for (int d = 0; d < 32; d++) {
            a0 += q2s[d] * row[d];
            a1 += q2s[32 + d] * row[32 + d];
        }
        sc[0][t] = a0 * ATT_SCALE;
        sc[1][t] = a1 * ATT_SCALE;
    }
    __syncthreads();
    for (int h = 0; h < 2; h++) {
        float mloc = -1e30f;
        for (int t = tid; t < 1024; t += 256) mloc = fmaxf(mloc, sc[h][t]);
        red[tid] = mloc;
        __syncthreads();
        for (int s = 128; s > 0; s >>= 1) {
            if (tid < s) red[tid] = fmaxf(red[tid], red[tid + s]);
            __syncthreads();
        }
        float mh = red[0];
        __syncthreads();
        float sum = 0.f;
        for (int t = tid; t < 1024; t += 256) {
            float e = __expf(sc[h][t] - mh);
            sc[h][t] = e;
            sum += e;
        }
        red[tid] = sum;
        __syncthreads();
        for (int s = 128; s > 0; s >>= 1) {
            if (tid < s) red[tid] += red[tid + s];
            __syncthreads();
        }
        if (tid == 0) sh2[h] = red[0];
        __syncthreads();
    }
    if (tid < 64) {
        int h = tid >> 5;
        const float* vcol = base + 128 + tid;
        float acc = 0.f;
        #pragma unroll 8
        for (int t = 0; t < 1024; t++) acc += sc[h][t] * vcol[(size_t)t * G3];
        os[tid] = acc / sh2[h];
    }
    __syncthreads();
    if (tid < 64) {
        float acc = out_b2[tid];
        #pragma unroll 8
        for (int d = 0; d < 64; d++) acc += os[d] * out_w2[tid * 64 + d];
        a2s[tid] = acc;
    }
    __syncthreads();
    if (tid < 32) {
        float acc = b_l[tid];
        #pragma unroll 8
        for (int d = 0; d < 64; d++) acc += a2s[d] * w_l[tid * 64 + d];
        hs[tid] = fmaxf(acc, 0.f);
    }
    __syncthreads();
    if (tid == 0) {
        float acc = b_l1[0];
        #pragma unroll
        for (int c = 0; c < 32; c++) acc += hs[c] * w_l1[c];
        out[b] = acc;
    }
}

// =====================================================================
extern "C" void kernel_launch(void* const* d_in, const int* in_sizes, int n_in,
                              void* d_out, int out_size) {
    const int*   atom_idx = (const int*)  d_in[0];
    const float* bond     = (const float*)d_in[1];
    const float* emb      = (const float*)d_in[2];
    const float* w_ih0    = (const float*)d_in[3];
    const float* w_hh0    = (const float*)d_in[4];
    const float* b_ih0    = (const float*)d_in[5];
    const float* b_hh0    = (const float*)d_in[6];
    const float* w_ih1    = (const float*)d_in[7];
    const float* w_hh1    = (const float*)d_in[8];
    const float* b_ih1    = (const float*)d_in[9];
    const float* b_hh1    = (const float*)d_in[10];
    const float* in_w1    = (const float*)d_in[11];
    const float* in_b1    = (const float*)d_in[12];
    const float* out_w1   = (const float*)d_in[13];
    const float* out_b1   = (const float*)d_in[14];
    const float* in_w2    = (const float*)d_in[15];
    const float* in_b2    = (const float*)d_in[16];
    const float* out_w2   = (const float*)d_in[17];
    const float* out_b2   = (const float*)d_in[18];
    const float* w_l      = (const float*)d_in[19];
    const float* b_l      = (const float*)d_in[20];
    const float* w_l1     = (const float*)d_in[21];
    const float* b_l1     = (const float*)d_in[22];
    float* outp = (float*)d_out;

    float *bufA, *bufB, *bufC, *wc, *bc;
    cudaGetSymbolAddress((void**)&bufA, g_bufA);
    cudaGetSymbolAddress((void**)&bufB, g_bufB);
    cudaGetSymbolAddress((void**)&bufC, g_bufC);
    cudaGetSymbolAddress((void**)&wc, g_wc);
    cudaGetSymbolAddress((void**)&bc, g_bc);

    // 0. fuse out-proj1 + qkv2 weights (independent of data path)
    k_fuse<<<48, 256>>>(in_w2, in_b2, out_w1, out_b1, wc, bc);
    // 1. embed + x@w_ih0^T -> bufA
    k_embed<<<(BB * TT) / 16, 192>>>(atom_idx, bond, emb, w_ih0, b_ih0, bufA);
    // 2. fused GRU x2 -> bufB
    k_gru<<<BB, 576>>>(bufA, w_hh0, b_hh0, w_ih1, b_ih1, w_hh1, b_hh1, bufB);
    // 3. qkv1 -> bufA
    {
        dim3 g((BB * TT) / 64, 3);
        k_gemm<<<g, 256>>>(bufB, in_w1, in_b1, bufA, G3);
    }
    // 4. flash attention layer 1 -> bufC
    k_flash<<<BB * 2 * (TT / 64), 256>>>(bufA, bufC);
    // 5. fused (out-proj1 + qkv2): attn1 @ Wc^T + bc -> bufA
    {
        dim3 g((BB * TT) / 64, 3);
        k_gemm<<<g, 256>>>(bufC, wc, bc, bufA, G3);
    }
    // 6. last-token attention 2 + head -> out
    k_final<<<BB, 256>>>(bufA, out_w2, out_b2, w_l, b_l, w_l1, b_l1, outp);
}